// round 2
// baseline (speedup 1.0000x reference)
#include <cuda_runtime.h>
#include <math.h>

// ---------------- problem constants ----------------
#define BSZ 4
#define NV  2048
#define NS  7
// layer dims
// fm0: 128, fm1: 128, fm2/3: 256, fm4: 512
// fuse = 128+128+256+256+512+512+16 = 1808, feat = 1296

// ---------------- device scratch ----------------
__device__ float g_d0[3*896];
__device__ float g_d1[3*896];
__device__ float g_d2[3*1792];
__device__ float g_d3[3*1792];
__device__ float g_d4[3*3584];

__device__ int   g_nb  [BSZ*NV*10];
__device__ int   g_nb1 [BSZ*512*10];
__device__ int   g_nb2 [BSZ*128*10];
__device__ int   g_nbp1[BSZ*512*4];
__device__ int   g_nbp2[BSZ*128*4];
__device__ int   g_n1  [BSZ*NV];
__device__ int   g_n2  [BSZ*NV];

__device__ float g_fm0[BSZ*NV*128];
__device__ float g_fo1[BSZ*NV*1024];
__device__ float g_cv1[BSZ*NV*128];
__device__ float g_fm1[BSZ*NV*128];
__device__ float g_fp1[BSZ*512*128];
__device__ float g_fo2[BSZ*512*2048];
__device__ float g_cv2[BSZ*512*256];
__device__ float g_fm2[BSZ*512*256];
__device__ float g_fo3[BSZ*512*2048];
__device__ float g_cv3[BSZ*512*256];
__device__ float g_fm3[BSZ*512*256];
__device__ float g_fp2[BSZ*128*256];
__device__ float g_fo4[BSZ*128*4096];
__device__ float g_fm4[BSZ*128*512];
__device__ float g_fg [BSZ*512];
__device__ float g_fuse[BSZ*NV*1808];
__device__ float g_h1 [BSZ*NV*512];
__device__ float g_h2 [BSZ*NV*512];
__device__ float g_pred[BSZ*NV*30];
__device__ float g_mean[256];
__device__ float g_var [256];

// ---------------- kernels ----------------

// normalize direction columns: dir is (3, D), per-column L2 normalize
__global__ void k_norm_dirs(const float* __restrict__ dir, float* __restrict__ out, int D) {
    int c = blockIdx.x * blockDim.x + threadIdx.x;
    if (c >= D) return;
    float x = dir[c], y = dir[D + c], z = dir[2 * D + c];
    float n = fmaxf(sqrtf(x * x + y * y + z * z), 1e-12f);
    float inv = 1.f / n;
    out[c] = x * inv; out[D + c] = y * inv; out[2 * D + c] = z * inv;
}

// kNN excluding self. pts: (B, bstride, 3); use first N points; Q queries (prefix).
template <int KN>
__global__ void k_knn(const float* __restrict__ pts, int bstride, int N, int Q,
                      int* __restrict__ out) {
    extern __shared__ float sp[];
    int b = blockIdx.y;
    const float* P = pts + (size_t)b * bstride * 3;
    for (int i = threadIdx.x; i < N * 3; i += blockDim.x) sp[i] = P[i];
    __syncthreads();
    int q = blockIdx.x * blockDim.x + threadIdx.x;
    if (q >= Q) return;
    float qx = sp[q * 3], qy = sp[q * 3 + 1], qz = sp[q * 3 + 2];
    float bd[KN]; int bi[KN];
#pragma unroll
    for (int i = 0; i < KN; i++) { bd[i] = 3.4e38f; bi[i] = 0; }
    for (int j = 0; j < N; j++) {
        if (j == q) continue;
        float dx = sp[j * 3] - qx, dy = sp[j * 3 + 1] - qy, dz = sp[j * 3 + 2] - qz;
        float d = dx * dx + dy * dy + dz * dz;
        if (d < bd[KN - 1]) {
            bd[KN - 1] = d; bi[KN - 1] = j;
#pragma unroll
            for (int r = KN - 1; r > 0; --r) {
                if (bd[r] < bd[r - 1]) {
                    float td = bd[r]; bd[r] = bd[r - 1]; bd[r - 1] = td;
                    int ti = bi[r]; bi[r] = bi[r - 1]; bi[r - 1] = ti;
                }
            }
        }
    }
    int* o = out + ((size_t)b * Q + q) * KN;
#pragma unroll
    for (int i = 0; i < KN; i++) o[i] = bi[i];
}

// nearest index: for each target (prefix Nt of pts), argmin over source prefix Ns
__global__ void k_nearest(const float* __restrict__ pts, int bstride, int Nt, int Ns,
                          int* __restrict__ out) {
    extern __shared__ float sp[];
    int b = blockIdx.y;
    const float* P = pts + (size_t)b * bstride * 3;
    for (int i = threadIdx.x; i < Ns * 3; i += blockDim.x) sp[i] = P[i];
    __syncthreads();
    int t = blockIdx.x * blockDim.x + threadIdx.x;
    if (t >= Nt) return;
    const float* T = pts + ((size_t)b * bstride + t) * 3;
    float qx = T[0], qy = T[1], qz = T[2];
    float best = 3.4e38f; int bi = 0;
    for (int j = 0; j < Ns; j++) {
        float dx = sp[j * 3] - qx, dy = sp[j * 3 + 1] - qy, dz = sp[j * 3 + 2] - qz;
        float d = dx * dx + dy * dy + dz * dz;
        if (d < best) { best = d; bi = j; }
    }
    out[(size_t)b * Nt + t] = bi;
}

// conv_surface -> fm0 (with relu). grid(V, B), block 128.
__global__ void k_conv_surface(const float* __restrict__ verts, const int* __restrict__ nb,
                               const float* __restrict__ sd, float* __restrict__ out) {
    int b = blockIdx.y, v = blockIdx.x;
    __shared__ float nd[10][3];
    size_t row = (size_t)b * NV + v;
    if (threadIdx.x < 10) {
        int j = nb[row * 10 + threadIdx.x];
        const float* c0 = verts + row * 3;
        const float* c1 = verts + ((size_t)b * NV + j) * 3;
        float dx = c1[0] - c0[0], dy = c1[1] - c0[1], dz = c1[2] - c0[2];
        float inv = 1.f / fmaxf(sqrtf(dx * dx + dy * dy + dz * dz), 1e-12f);
        nd[threadIdx.x][0] = dx * inv; nd[threadIdx.x][1] = dy * inv; nd[threadIdx.x][2] = dz * inv;
    }
    __syncthreads();
    int c = threadIdx.x;
    float acc = 0.f;
#pragma unroll
    for (int s = 0; s < 7; s++) {
        int col = s * 128 + c;
        float sx = sd[col], sy = sd[896 + col], sz = sd[1792 + col];
        float m = 0.f;  // max over relu'd dots: init 0 == relu fold
#pragma unroll
        for (int n = 0; n < 10; n++) {
            float t = nd[n][0] * sx + nd[n][1] * sy + nd[n][2] * sz;
            m = fmaxf(m, t);
        }
        acc += m;
    }
    out[row * 128 + c] = fmaxf(acc, 0.f);
}

// conv_layer: out = center + sum_s max_n relu(nd.sd)*supp. grid(V,B), block OC.
__global__ void k_conv_layer(const float* __restrict__ verts, int vstride, int V,
                             const int* __restrict__ nb, const float* __restrict__ fo,
                             const float* __restrict__ sd, int OC, float* __restrict__ out) {
    int b = blockIdx.y, v = blockIdx.x;
    __shared__ float nd[10][3];
    __shared__ int nidx[10];
    if (threadIdx.x < 10) {
        int j = nb[((size_t)b * V + v) * 10 + threadIdx.x];
        nidx[threadIdx.x] = j;
        const float* c0 = verts + ((size_t)b * vstride + v) * 3;
        const float* c1 = verts + ((size_t)b * vstride + j) * 3;
        float dx = c1[0] - c0[0], dy = c1[1] - c0[1], dz = c1[2] - c0[2];
        float inv = 1.f / fmaxf(sqrtf(dx * dx + dy * dy + dz * dz), 1e-12f);
        nd[threadIdx.x][0] = dx * inv; nd[threadIdx.x][1] = dy * inv; nd[threadIdx.x][2] = dz * inv;
    }
    __syncthreads();
    int c = threadIdx.x;
    int FW = 8 * OC, D = 7 * OC;
    const float* base = fo + (size_t)b * V * FW;
    float acc = base[(size_t)v * FW + c];
#pragma unroll
    for (int s = 0; s < 7; s++) {
        int col = s * OC + c;
        float sx = sd[col], sy = sd[D + col], sz = sd[2 * D + col];
        float m = -3.4e38f;
#pragma unroll
        for (int n = 0; n < 10; n++) {
            float t = fmaxf(nd[n][0] * sx + nd[n][1] * sy + nd[n][2] * sz, 0.f);
            float sup = base[(size_t)nidx[n] * FW + OC + col];
            m = fmaxf(m, t * sup);
        }
        acc += m;
    }
    out[((size_t)b * V + v) * OC + c] = acc;
}

// BN stats: x is (R, C). grid(C/32), block(32,8).
__global__ void k_bn_stats(const float* __restrict__ x, int R, int C,
                           float* __restrict__ mean, float* __restrict__ var) {
    int c = blockIdx.x * 32 + threadIdx.x;
    float s = 0.f, s2 = 0.f;
    for (int r = threadIdx.y; r < R; r += 8) {
        float v = x[(size_t)r * C + c];
        s += v; s2 += v * v;
    }
    __shared__ float sh[8][32], sh2[8][32];
    sh[threadIdx.y][threadIdx.x] = s; sh2[threadIdx.y][threadIdx.x] = s2;
    __syncthreads();
    if (threadIdx.y == 0) {
        float ts = 0.f, ts2 = 0.f;
#pragma unroll
        for (int y = 0; y < 8; y++) { ts += sh[y][threadIdx.x]; ts2 += sh2[y][threadIdx.x]; }
        float m = ts / (float)R;
        mean[c] = m;
        var[c] = ts2 / (float)R - m * m;
    }
}

__global__ void k_bn_apply(const float* __restrict__ x, const float* __restrict__ mean,
                           const float* __restrict__ var, const float* __restrict__ g,
                           const float* __restrict__ be, float* __restrict__ y,
                           int total, int C) {
    int i = blockIdx.x * blockDim.x + threadIdx.x;
    if (i >= total) return;
    int c = i % C;
    float v = (x[i] - mean[c]) * rsqrtf(var[c] + 1e-5f) * g[c] + be[c];
    y[i] = fmaxf(v, 0.f);
}

// pool: max over 4 neighbors. grid(P, B), block C.
__global__ void k_pool(const float* __restrict__ fm, int Vin, const int* __restrict__ nbp,
                       int C, float* __restrict__ out) {
    int b = blockIdx.y, p = blockIdx.x, c = threadIdx.x;
    int P = gridDim.x;
    const int* nr = nbp + ((size_t)b * P + p) * 4;
    float m = -3.4e38f;
#pragma unroll
    for (int j = 0; j < 4; j++)
        m = fmaxf(m, fm[((size_t)b * Vin + nr[j]) * C + c]);
    out[((size_t)b * P + p) * C + c] = m;
}

// global max over 128 rows of fm4 (B,128,512)
__global__ void k_fglobal(const float* __restrict__ fm4, float* __restrict__ fg) {
    int b = blockIdx.x, c = threadIdx.x;
    float m = -3.4e38f;
    for (int r = 0; r < 128; r++)
        m = fmaxf(m, fm4[((size_t)b * 128 + r) * 512 + c]);
    fg[b * 512 + c] = m;
}

// assemble fuse (1808) + feat (1296 -> d_out). grid(V,B), block 256.
__global__ void k_assemble(const float* __restrict__ fm0, const float* __restrict__ fm1,
                           const float* __restrict__ fm2, const float* __restrict__ fm3,
                           const float* __restrict__ fm4, const float* __restrict__ fg,
                           const float* __restrict__ onehot, const int* __restrict__ n1,
                           const int* __restrict__ n2, float* __restrict__ fuse,
                           float* __restrict__ feat) {
    int b = blockIdx.y, v = blockIdx.x;
    size_t row = (size_t)b * NV + v;
    int i1 = n1[row], i2 = n2[row];
    float* fu = fuse + row * 1808;
    float* fe = feat + row * 1296;
    for (int c = threadIdx.x; c < 1808; c += blockDim.x) {
        float val;
        if (c < 128)        val = fm0[row * 128 + c];
        else if (c < 256)   val = fm1[row * 128 + (c - 128)];
        else if (c < 512)   val = fm2[((size_t)b * 512 + i1) * 256 + (c - 256)];
        else if (c < 768)   val = fm3[((size_t)b * 512 + i1) * 256 + (c - 512)];
        else if (c < 1280)  val = fm4[((size_t)b * 128 + i2) * 512 + (c - 768)];
        else if (c < 1792)  val = fg[b * 512 + (c - 1280)];
        else                val = onehot[b * 16 + (c - 1792)];
        fu[c] = val;
        if (c < 1280)       fe[c] = val;
        else if (c >= 1792) fe[1280 + (c - 1792)] = val;
    }
}

// SGEMM: C = A(MxK) * B + bias, B either (K,N) or, if BT, (N,K) row-major.
// 64x64 tile, BK=16, 256 threads, 4x4 micro-tile.
#define BM 64
#define BN 64
#define BKK 16
template <bool BT, bool RELU>
__global__ void k_gemm(const float* __restrict__ A, const float* __restrict__ B,
                       const float* __restrict__ bias, float* __restrict__ C,
                       int M, int N, int K) {
    __shared__ __align__(16) float As[BKK][BM + 4];
    __shared__ __align__(16) float Bs[BKK][BN + 4];
    int bm = blockIdx.y * BM, bn = blockIdx.x * BN;
    int tid = threadIdx.x;
    int tx = tid & 15, ty = tid >> 4;
    float acc[4][4] = {};
    for (int k0 = 0; k0 < K; k0 += BKK) {
#pragma unroll
        for (int i = 0; i < 4; i++) {
            int idx = tid + i * 256;
            int r = idx >> 4, kk = idx & 15;
            int gr = bm + r;
            As[kk][r] = (gr < M) ? A[(size_t)gr * K + k0 + kk] : 0.f;
        }
#pragma unroll
        for (int i = 0; i < 4; i++) {
            int idx = tid + i * 256;
            if (!BT) {
                int kk = idx >> 6, n = idx & 63;
                int gn = bn + n;
                Bs[kk][n] = (gn < N) ? B[(size_t)(k0 + kk) * N + gn] : 0.f;
            } else {
                int n = idx >> 4, kk = idx & 15;
                int gn = bn + n;
                Bs[kk][n] = (gn < N) ? B[(size_t)gn * K + k0 + kk] : 0.f;
            }
        }
        __syncthreads();
#pragma unroll
        for (int kk = 0; kk < BKK; kk++) {
            float4 av = *reinterpret_cast<const float4*>(&As[kk][ty * 4]);
            float4 bv = *reinterpret_cast<const float4*>(&Bs[kk][tx * 4]);
            float a[4] = {av.x, av.y, av.z, av.w};
            float bb[4] = {bv.x, bv.y, bv.z, bv.w};
#pragma unroll
            for (int i = 0; i < 4; i++)
#pragma unroll
                for (int j = 0; j < 4; j++)
                    acc[i][j] += a[i] * bb[j];
        }
        __syncthreads();
    }
#pragma unroll
    for (int i = 0; i < 4; i++) {
        int gr = bm + ty * 4 + i;
        if (gr >= M) continue;
#pragma unroll
        for (int j = 0; j < 4; j++) {
            int gn = bn + tx * 4 + j;
            if (gn >= N) continue;
            float v = acc[i][j] + bias[gn];
            if (RELU) v = fmaxf(v, 0.f);
            C[(size_t)gr * N + gn] = v;
        }
    }
}

// split pred (rows x 30) into seg (rows x 6) and vecs (rows x 24)
__global__ void k_split(const float* __restrict__ pred, float* __restrict__ out) {
    int row = blockIdx.x;
    int t = threadIdx.x;
    if (t < 6)
        out[(size_t)row * 6 + t] = pred[(size_t)row * 30 + t];
    else if (t < 30)
        out[(size_t)BSZ * NV * 6 + (size_t)row * 24 + (t - 6)] = pred[(size_t)row * 30 + t];
}

// ---------------- host ----------------
static inline int cdiv(int a, int b) { return (a + b - 1) / b; }

#define SYMF(p, s) do { void* _t; cudaGetSymbolAddress(&_t, s); p = (float*)_t; } while (0)
#define SYMI(p, s) do { void* _t; cudaGetSymbolAddress(&_t, s); p = (int*)_t; } while (0)

extern "C" void kernel_launch(void* const* d_in, const int* in_sizes, int n_in,
                              void* d_out, int out_size) {
    const float* vertices = (const float*)d_in[0];
    const float* onehot   = (const float*)d_in[1];
    const float* dir0 = (const float*)d_in[2];
    const float* w1   = (const float*)d_in[3];
    const float* b1   = (const float*)d_in[4];
    const float* dir1 = (const float*)d_in[5];
    const float* w2   = (const float*)d_in[6];
    const float* b2   = (const float*)d_in[7];
    const float* dir2 = (const float*)d_in[8];
    const float* w3   = (const float*)d_in[9];
    const float* b3   = (const float*)d_in[10];
    const float* dir3 = (const float*)d_in[11];
    const float* w4   = (const float*)d_in[12];
    const float* b4   = (const float*)d_in[13];
    const float* dir4 = (const float*)d_in[14];
    const float* g_bn1 = (const float*)d_in[15];
    const float* be_bn1 = (const float*)d_in[16];
    const float* g_bn2 = (const float*)d_in[17];
    const float* be_bn2 = (const float*)d_in[18];
    const float* g_bn3 = (const float*)d_in[19];
    const float* be_bn3 = (const float*)d_in[20];
    const float* wc1 = (const float*)d_in[21];
    const float* bc1 = (const float*)d_in[22];
    const float* wc2 = (const float*)d_in[23];
    const float* bc2 = (const float*)d_in[24];
    const float* wc3 = (const float*)d_in[25];
    const float* bc3 = (const float*)d_in[26];
    float* out = (float*)d_out;

    float *p_d0, *p_d1, *p_d2, *p_d3, *p_d4;
    SYMF(p_d0, g_d0); SYMF(p_d1, g_d1); SYMF(p_d2, g_d2); SYMF(p_d3, g_d3); SYMF(p_d4, g_d4);
    int *p_nb, *p_nb1, *p_nb2, *p_nbp1, *p_nbp2, *p_n1, *p_n2;
    SYMI(p_nb, g_nb); SYMI(p_nb1, g_nb1); SYMI(p_nb2, g_nb2);
    SYMI(p_nbp1, g_nbp1); SYMI(p_nbp2, g_nbp2); SYMI(p_n1, g_n1); SYMI(p_n2, g_n2);
    float *p_fm0, *p_fo1, *p_cv1, *p_fm1, *p_fp1, *p_fo2, *p_cv2, *p_fm2;
    float *p_fo3, *p_cv3, *p_fm3, *p_fp2, *p_fo4, *p_fm4, *p_fg, *p_fuse, *p_h1, *p_h2, *p_pred;
    float *p_mean, *p_var;
    SYMF(p_fm0, g_fm0); SYMF(p_fo1, g_fo1); SYMF(p_cv1, g_cv1); SYMF(p_fm1, g_fm1);
    SYMF(p_fp1, g_fp1); SYMF(p_fo2, g_fo2); SYMF(p_cv2, g_cv2); SYMF(p_fm2, g_fm2);
    SYMF(p_fo3, g_fo3); SYMF(p_cv3, g_cv3); SYMF(p_fm3, g_fm3); SYMF(p_fp2, g_fp2);
    SYMF(p_fo4, g_fo4); SYMF(p_fm4, g_fm4); SYMF(p_fg, g_fg); SYMF(p_fuse, g_fuse);
    SYMF(p_h1, g_h1); SYMF(p_h2, g_h2); SYMF(p_pred, g_pred);
    SYMF(p_mean, g_mean); SYMF(p_var, g_var);

    // 0) normalize direction banks
    k_norm_dirs<<<cdiv(896, 256), 256>>>(dir0, p_d0, 896);
    k_norm_dirs<<<cdiv(896, 256), 256>>>(dir1, p_d1, 896);
    k_norm_dirs<<<cdiv(1792, 256), 256>>>(dir2, p_d2, 1792);
    k_norm_dirs<<<cdiv(1792, 256), 256>>>(dir3, p_d3, 1792);
    k_norm_dirs<<<cdiv(3584, 256), 256>>>(dir4, p_d4, 3584);

    // 1) kNN graphs
    k_knn<10><<<dim3(cdiv(NV, 128), BSZ), 128, NV * 3 * 4>>>(vertices, NV, NV, NV, p_nb);
    k_knn<4><<<dim3(cdiv(512, 128), BSZ), 128, NV * 3 * 4>>>(vertices, NV, NV, 512, p_nbp1);
    k_knn<10><<<dim3(cdiv(512, 128), BSZ), 128, 512 * 3 * 4>>>(vertices, NV, 512, 512, p_nb1);
    k_knn<4><<<dim3(1, BSZ), 128, 512 * 3 * 4>>>(vertices, NV, 512, 128, p_nbp2);
    k_knn<10><<<dim3(1, BSZ), 128, 128 * 3 * 4>>>(vertices, NV, 128, 128, p_nb2);

    // 2) conv_surface -> fm0
    k_conv_surface<<<dim3(NV, BSZ), 128>>>(vertices, p_nb, p_d0, p_fm0);

    // 3) layer1: fo1 = fm0 @ w1 + b1 ; conv ; BN ; relu
    k_gemm<false, false><<<dim3(cdiv(1024, BN), cdiv(BSZ * NV, BM)), 256>>>(
        p_fm0, w1, b1, p_fo1, BSZ * NV, 1024, 128);
    k_conv_layer<<<dim3(NV, BSZ), 128>>>(vertices, NV, NV, p_nb, p_fo1, p_d1, 128, p_cv1);
    k_bn_stats<<<128 / 32, dim3(32, 8)>>>(p_cv1, BSZ * NV, 128, p_mean, p_var);
    k_bn_apply<<<cdiv(BSZ * NV * 128, 256), 256>>>(p_cv1, p_mean, p_var, g_bn1, be_bn1,
                                                   p_fm1, BSZ * NV * 128, 128);

    // 4) pool1 -> fp1 (512 x 128)
    k_pool<<<dim3(512, BSZ), 128>>>(p_fm1, NV, p_nbp1, 128, p_fp1);

    // 5) layer2
    k_gemm<false, false><<<dim3(cdiv(2048, BN), cdiv(BSZ * 512, BM)), 256>>>(
        p_fp1, w2, b2, p_fo2, BSZ * 512, 2048, 128);
    k_conv_layer<<<dim3(512, BSZ), 256>>>(vertices, NV, 512, p_nb1, p_fo2, p_d2, 256, p_cv2);
    k_bn_stats<<<256 / 32, dim3(32, 8)>>>(p_cv2, BSZ * 512, 256, p_mean, p_var);
    k_bn_apply<<<cdiv(BSZ * 512 * 256, 256), 256>>>(p_cv2, p_mean, p_var, g_bn2, be_bn2,
                                                    p_fm2, BSZ * 512 * 256, 256);

    // 6) layer3
    k_gemm<false, false><<<dim3(cdiv(2048, BN), cdiv(BSZ * 512, BM)), 256>>>(
        p_fm2, w3, b3, p_fo3, BSZ * 512, 2048, 256);
    k_conv_layer<<<dim3(512, BSZ), 256>>>(vertices, NV, 512, p_nb1, p_fo3, p_d3, 256, p_cv3);
    k_bn_stats<<<256 / 32, dim3(32, 8)>>>(p_cv3, BSZ * 512, 256, p_mean, p_var);
    k_bn_apply<<<cdiv(BSZ * 512 * 256, 256), 256>>>(p_cv3, p_mean, p_var, g_bn3, be_bn3,
                                                    p_fm3, BSZ * 512 * 256, 256);

    // 7) pool2 -> fp2 (128 x 256)
    k_pool<<<dim3(128, BSZ), 256>>>(p_fm3, 512, p_nbp2, 256, p_fp2);

    // 8) layer4 (no BN/relu)
    k_gemm<false, false><<<dim3(cdiv(4096, BN), cdiv(BSZ * 128, BM)), 256>>>(
        p_fp2, w4, b4, p_fo4, BSZ * 128, 4096, 256);
    k_conv_layer<<<dim3(128, BSZ), 512>>>(vertices, NV, 128, p_nb2, p_fo4, p_d4, 512, p_fm4);

    // 9) global max feature
    k_fglobal<<<BSZ, 512>>>(p_fm4, p_fg);

    // 10) nearest indices for upsampling
    k_nearest<<<dim3(cdiv(NV, 128), BSZ), 128, 512 * 3 * 4>>>(vertices, NV, NV, 512, p_n1);
    k_nearest<<<dim3(cdiv(NV, 128), BSZ), 128, 128 * 3 * 4>>>(vertices, NV, NV, 128, p_n2);

    // 11) assemble fuse + write feat to d_out
    float* feat_out = out + (size_t)BSZ * NV * 6 + (size_t)BSZ * NV * 24;
    k_assemble<<<dim3(NV, BSZ), 256>>>(p_fm0, p_fm1, p_fm2, p_fm3, p_fm4, p_fg, onehot,
                                       p_n1, p_n2, p_fuse, feat_out);

    // 12) final MLP
    k_gemm<true, true><<<dim3(cdiv(512, BN), cdiv(BSZ * NV, BM)), 256>>>(
        p_fuse, wc1, bc1, p_h1, BSZ * NV, 512, 1808);
    k_gemm<true, true><<<dim3(cdiv(512, BN), cdiv(BSZ * NV, BM)), 256>>>(
        p_h1, wc2, bc2, p_h2, BSZ * NV, 512, 512);
    k_gemm<true, false><<<dim3(cdiv(30, BN), cdiv(BSZ * NV, BM)), 256>>>(
        p_h2, wc3, bc3, p_pred, BSZ * NV, 30, 512);

    // 13) split seg / vecs into d_out
    k_split<<<BSZ * NV, 32>>>(p_pred, out);
}

// round 3
// speedup vs baseline: 1.1271x; 1.1271x over previous
#include <cuda_runtime.h>
#include <math.h>

// ---------------- problem constants ----------------
#define BSZ 4
#define NV  2048

// ---------------- device scratch ----------------
__device__ float g_d0[3*896];
__device__ float g_d1[3*896];
__device__ float g_d2[3*1792];
__device__ float g_d3[3*1792];
__device__ float g_d4[3*3584];

__device__ int   g_nb  [BSZ*NV*10];
__device__ int   g_nb1 [BSZ*512*10];
__device__ int   g_nb2 [BSZ*128*10];
__device__ int   g_nbp1[BSZ*512*4];
__device__ int   g_nbp2[BSZ*128*4];
__device__ int   g_n1  [BSZ*NV];
__device__ int   g_n2  [BSZ*NV];

__device__ float g_fm0[BSZ*NV*128];
__device__ float g_fo1[BSZ*NV*1024];
__device__ float g_cv1[BSZ*NV*128];
__device__ float g_fm1[BSZ*NV*128];
__device__ float g_fp1[BSZ*512*128];
__device__ float g_fo2[BSZ*512*2048];
__device__ float g_cv2[BSZ*512*256];
__device__ float g_fm2[BSZ*512*256];
__device__ float g_fo3[BSZ*512*2048];
__device__ float g_cv3[BSZ*512*256];
__device__ float g_fm3[BSZ*512*256];
__device__ float g_fp2[BSZ*128*256];
__device__ float g_fo4[BSZ*128*4096];
__device__ float g_fm4[BSZ*128*512];
__device__ float g_fg [BSZ*512];
__device__ float g_fuse[BSZ*NV*1808];
__device__ float g_h1 [BSZ*NV*512];
__device__ float g_h2 [BSZ*NV*512];
__device__ float g_pred[BSZ*NV*30];
__device__ float g_mean[256];
__device__ float g_var [256];

// ---------------- kernels ----------------

__global__ void k_norm_dirs(const float* __restrict__ dir, float* __restrict__ out, int D) {
    int c = blockIdx.x * blockDim.x + threadIdx.x;
    if (c >= D) return;
    float x = dir[c], y = dir[D + c], z = dir[2 * D + c];
    float n = fmaxf(sqrtf(x * x + y * y + z * z), 1e-12f);
    float inv = 1.f / n;
    out[c] = x * inv; out[D + c] = y * inv; out[2 * D + c] = z * inv;
}

template <int KN>
__global__ void k_knn(const float* __restrict__ pts, int bstride, int N, int Q,
                      int* __restrict__ out) {
    extern __shared__ float sp[];
    int b = blockIdx.y;
    const float* P = pts + (size_t)b * bstride * 3;
    for (int i = threadIdx.x; i < N * 3; i += blockDim.x) sp[i] = P[i];
    __syncthreads();
    int q = blockIdx.x * blockDim.x + threadIdx.x;
    if (q >= Q) return;
    float qx = sp[q * 3], qy = sp[q * 3 + 1], qz = sp[q * 3 + 2];
    float bd[KN]; int bi[KN];
#pragma unroll
    for (int i = 0; i < KN; i++) { bd[i] = 3.4e38f; bi[i] = 0; }
    for (int j = 0; j < N; j++) {
        if (j == q) continue;
        float dx = sp[j * 3] - qx, dy = sp[j * 3 + 1] - qy, dz = sp[j * 3 + 2] - qz;
        float d = dx * dx + dy * dy + dz * dz;
        if (d < bd[KN - 1]) {
            bd[KN - 1] = d; bi[KN - 1] = j;
#pragma unroll
            for (int r = KN - 1; r > 0; --r) {
                if (bd[r] < bd[r - 1]) {
                    float td = bd[r]; bd[r] = bd[r - 1]; bd[r - 1] = td;
                    int ti = bi[r]; bi[r] = bi[r - 1]; bi[r - 1] = ti;
                }
            }
        }
    }
    int* o = out + ((size_t)b * Q + q) * KN;
#pragma unroll
    for (int i = 0; i < KN; i++) o[i] = bi[i];
}

__global__ void k_nearest(const float* __restrict__ pts, int bstride, int Nt, int Ns,
                          int* __restrict__ out) {
    extern __shared__ float sp[];
    int b = blockIdx.y;
    const float* P = pts + (size_t)b * bstride * 3;
    for (int i = threadIdx.x; i < Ns * 3; i += blockDim.x) sp[i] = P[i];
    __syncthreads();
    int t = blockIdx.x * blockDim.x + threadIdx.x;
    if (t >= Nt) return;
    const float* T = pts + ((size_t)b * bstride + t) * 3;
    float qx = T[0], qy = T[1], qz = T[2];
    float best = 3.4e38f; int bi = 0;
    for (int j = 0; j < Ns; j++) {
        float dx = sp[j * 3] - qx, dy = sp[j * 3 + 1] - qy, dz = sp[j * 3 + 2] - qz;
        float d = dx * dx + dy * dy + dz * dz;
        if (d < best) { best = d; bi = j; }
    }
    out[(size_t)b * Nt + t] = bi;
}

__global__ void k_conv_surface(const float* __restrict__ verts, const int* __restrict__ nb,
                               const float* __restrict__ sd, float* __restrict__ out) {
    int b = blockIdx.y, v = blockIdx.x;
    __shared__ float nd[10][3];
    size_t row = (size_t)b * NV + v;
    if (threadIdx.x < 10) {
        int j = nb[row * 10 + threadIdx.x];
        const float* c0 = verts + row * 3;
        const float* c1 = verts + ((size_t)b * NV + j) * 3;
        float dx = c1[0] - c0[0], dy = c1[1] - c0[1], dz = c1[2] - c0[2];
        float inv = 1.f / fmaxf(sqrtf(dx * dx + dy * dy + dz * dz), 1e-12f);
        nd[threadIdx.x][0] = dx * inv; nd[threadIdx.x][1] = dy * inv; nd[threadIdx.x][2] = dz * inv;
    }
    __syncthreads();
    int c = threadIdx.x;
    float acc = 0.f;
#pragma unroll
    for (int s = 0; s < 7; s++) {
        int col = s * 128 + c;
        float sx = sd[col], sy = sd[896 + col], sz = sd[1792 + col];
        float m = 0.f;
#pragma unroll
        for (int n = 0; n < 10; n++) {
            float t = nd[n][0] * sx + nd[n][1] * sy + nd[n][2] * sz;
            m = fmaxf(m, t);
        }
        acc += m;
    }
    out[row * 128 + c] = fmaxf(acc, 0.f);
}

__global__ void k_conv_layer(const float* __restrict__ verts, int vstride, int V,
                             const int* __restrict__ nb, const float* __restrict__ fo,
                             const float* __restrict__ sd, int OC, float* __restrict__ out) {
    int b = blockIdx.y, v = blockIdx.x;
    __shared__ float nd[10][3];
    __shared__ int nidx[10];
    if (threadIdx.x < 10) {
        int j = nb[((size_t)b * V + v) * 10 + threadIdx.x];
        nidx[threadIdx.x] = j;
        const float* c0 = verts + ((size_t)b * vstride + v) * 3;
        const float* c1 = verts + ((size_t)b * vstride + j) * 3;
        float dx = c1[0] - c0[0], dy = c1[1] - c0[1], dz = c1[2] - c0[2];
        float inv = 1.f / fmaxf(sqrtf(dx * dx + dy * dy + dz * dz), 1e-12f);
        nd[threadIdx.x][0] = dx * inv; nd[threadIdx.x][1] = dy * inv; nd[threadIdx.x][2] = dz * inv;
    }
    __syncthreads();
    int c = threadIdx.x;
    int FW = 8 * OC, D = 7 * OC;
    const float* base = fo + (size_t)b * V * FW;
    float acc = base[(size_t)v * FW + c];
#pragma unroll
    for (int s = 0; s < 7; s++) {
        int col = s * OC + c;
        float sx = sd[col], sy = sd[D + col], sz = sd[2 * D + col];
        float m = -3.4e38f;
#pragma unroll
        for (int n = 0; n < 10; n++) {
            float t = fmaxf(nd[n][0] * sx + nd[n][1] * sy + nd[n][2] * sz, 0.f);
            float sup = base[(size_t)nidx[n] * FW + OC + col];
            m = fmaxf(m, t * sup);
        }
        acc += m;
    }
    out[((size_t)b * V + v) * OC + c] = acc;
}

__global__ void k_bn_stats(const float* __restrict__ x, int R, int C,
                           float* __restrict__ mean, float* __restrict__ var) {
    int c = blockIdx.x * 32 + threadIdx.x;
    float s = 0.f, s2 = 0.f;
    for (int r = threadIdx.y; r < R; r += 8) {
        float v = x[(size_t)r * C + c];
        s += v; s2 += v * v;
    }
    __shared__ float sh[8][32], sh2[8][32];
    sh[threadIdx.y][threadIdx.x] = s; sh2[threadIdx.y][threadIdx.x] = s2;
    __syncthreads();
    if (threadIdx.y == 0) {
        float ts = 0.f, ts2 = 0.f;
#pragma unroll
        for (int y = 0; y < 8; y++) { ts += sh[y][threadIdx.x]; ts2 += sh2[y][threadIdx.x]; }
        float m = ts / (float)R;
        mean[c] = m;
        var[c] = ts2 / (float)R - m * m;
    }
}

__global__ void k_bn_apply(const float* __restrict__ x, const float* __restrict__ mean,
                           const float* __restrict__ var, const float* __restrict__ g,
                           const float* __restrict__ be, float* __restrict__ y,
                           int total, int C) {
    int i = blockIdx.x * blockDim.x + threadIdx.x;
    if (i >= total) return;
    int c = i % C;
    float v = (x[i] - mean[c]) * rsqrtf(var[c] + 1e-5f) * g[c] + be[c];
    y[i] = fmaxf(v, 0.f);
}

__global__ void k_pool(const float* __restrict__ fm, int Vin, const int* __restrict__ nbp,
                       int C, float* __restrict__ out) {
    int b = blockIdx.y, p = blockIdx.x, c = threadIdx.x;
    int P = gridDim.x;
    const int* nr = nbp + ((size_t)b * P + p) * 4;
    float m = -3.4e38f;
#pragma unroll
    for (int j = 0; j < 4; j++)
        m = fmaxf(m, fm[((size_t)b * Vin + nr[j]) * C + c]);
    out[((size_t)b * P + p) * C + c] = m;
}

__global__ void k_fglobal(const float* __restrict__ fm4, float* __restrict__ fg) {
    int b = blockIdx.x, c = threadIdx.x;
    float m = -3.4e38f;
    for (int r = 0; r < 128; r++)
        m = fmaxf(m, fm4[((size_t)b * 128 + r) * 512 + c]);
    fg[b * 512 + c] = m;
}

__global__ void k_assemble(const float* __restrict__ fm0, const float* __restrict__ fm1,
                           const float* __restrict__ fm2, const float* __restrict__ fm3,
                           const float* __restrict__ fm4, const float* __restrict__ fg,
                           const float* __restrict__ onehot, const int* __restrict__ n1,
                           const int* __restrict__ n2, float* __restrict__ fuse,
                           float* __restrict__ feat) {
    int b = blockIdx.y, v = blockIdx.x;
    size_t row = (size_t)b * NV + v;
    int i1 = n1[row], i2 = n2[row];
    float* fu = fuse + row * 1808;
    float* fe = feat + row * 1296;
    for (int c = threadIdx.x; c < 1808; c += blockDim.x) {
        float val;
        if (c < 128)        val = fm0[row * 128 + c];
        else if (c < 256)   val = fm1[row * 128 + (c - 128)];
        else if (c < 512)   val = fm2[((size_t)b * 512 + i1) * 256 + (c - 256)];
        else if (c < 768)   val = fm3[((size_t)b * 512 + i1) * 256 + (c - 512)];
        else if (c < 1280)  val = fm4[((size_t)b * 128 + i2) * 512 + (c - 768)];
        else if (c < 1792)  val = fg[b * 512 + (c - 1280)];
        else                val = onehot[b * 16 + (c - 1792)];
        fu[c] = val;
        if (c < 1280)       fe[c] = val;
        else if (c >= 1792) fe[1280 + (c - 1792)] = val;
    }
}

// ---------------- big SGEMM: 128x128 tile, BK=8, 8x8 microtile, double buffered ----
// Requires M%128==0, N%128==0, K%8==0. B either (K,N) row-major or (N,K) if BT.
#define GBM 128
#define GBN 128
#define GBK 8
template <bool BT, bool RELU>
__global__ void __launch_bounds__(256)
k_gemm_big(const float* __restrict__ A, const float* __restrict__ B,
           const float* __restrict__ bias, float* __restrict__ C,
           int M, int N, int K) {
    __shared__ __align__(16) float As[2][GBK][GBM];
    __shared__ __align__(16) float Bs[2][GBK][GBN];
    int bm = blockIdx.y * GBM, bn = blockIdx.x * GBN;
    int tid = threadIdx.x;
    int tx = tid & 15, ty = tid >> 4;

    // A (and BT-B) staging: row = tid/2 (0..127), 4 consecutive k at (tid&1)*4
    int a_r = tid >> 1;
    int a_c = (tid & 1) * 4;
    // B (no transpose) staging: k-row = tid/32 (0..7), 4 cols at (tid&31)*4
    int b_r = tid >> 5;
    int b_c = (tid & 31) * 4;

    const float* Arow = A + (size_t)(bm + a_r) * K + a_c;
    const float* Brow_t = BT ? (B + (size_t)(bn + a_r) * K + a_c) : nullptr;
    const float* Brow_n = BT ? nullptr : (B + (size_t)b_r * N + bn + b_c);

    float4 areg = *reinterpret_cast<const float4*>(Arow);
    float4 breg = BT ? *reinterpret_cast<const float4*>(Brow_t)
                     : *reinterpret_cast<const float4*>(Brow_n);

    As[0][a_c + 0][a_r] = areg.x; As[0][a_c + 1][a_r] = areg.y;
    As[0][a_c + 2][a_r] = areg.z; As[0][a_c + 3][a_r] = areg.w;
    if (BT) {
        Bs[0][a_c + 0][a_r] = breg.x; Bs[0][a_c + 1][a_r] = breg.y;
        Bs[0][a_c + 2][a_r] = breg.z; Bs[0][a_c + 3][a_r] = breg.w;
    } else {
        *reinterpret_cast<float4*>(&Bs[0][b_r][b_c]) = breg;
    }
    __syncthreads();

    float acc[8][8] = {};
    int nT = K / GBK;
    for (int t = 0; t < nT; t++) {
        int buf = t & 1;
        if (t + 1 < nT) {
            int k0 = (t + 1) * GBK;
            areg = *reinterpret_cast<const float4*>(Arow + k0);
            breg = BT ? *reinterpret_cast<const float4*>(Brow_t + k0)
                      : *reinterpret_cast<const float4*>(Brow_n + (size_t)k0 * N);
        }
#pragma unroll
        for (int kk = 0; kk < GBK; kk++) {
            float4 av0 = *reinterpret_cast<const float4*>(&As[buf][kk][ty * 8]);
            float4 av1 = *reinterpret_cast<const float4*>(&As[buf][kk][ty * 8 + 4]);
            float4 bv0 = *reinterpret_cast<const float4*>(&Bs[buf][kk][tx * 8]);
            float4 bv1 = *reinterpret_cast<const float4*>(&Bs[buf][kk][tx * 8 + 4]);
            float ar[8] = {av0.x, av0.y, av0.z, av0.w, av1.x, av1.y, av1.z, av1.w};
            float br[8] = {bv0.x, bv0.y, bv0.z, bv0.w, bv1.x, bv1.y, bv1.z, bv1.w};
#pragma unroll
            for (int i = 0; i < 8; i++)
#pragma unroll
                for (int j = 0; j < 8; j++)
                    acc[i][j] = fmaf(ar[i], br[j], acc[i][j]);
        }
        if (t + 1 < nT) {
            int nb = (t + 1) & 1;
            As[nb][a_c + 0][a_r] = areg.x; As[nb][a_c + 1][a_r] = areg.y;
            As[nb][a_c + 2][a_r] = areg.z; As[nb][a_c + 3][a_r] = areg.w;
            if (BT) {
                Bs[nb][a_c + 0][a_r] = breg.x; Bs[nb][a_c + 1][a_r] = breg.y;
                Bs[nb][a_c + 2][a_r] = breg.z; Bs[nb][a_c + 3][a_r] = breg.w;
            } else {
                *reinterpret_cast<float4*>(&Bs[nb][b_r][b_c]) = breg;
            }
            __syncthreads();
        }
    }

    float bz[8];
#pragma unroll
    for (int j = 0; j < 8; j++) bz[j] = bias[bn + tx * 8 + j];
#pragma unroll
    for (int i = 0; i < 8; i++) {
        size_t gr = (size_t)(bm + ty * 8 + i) * N + bn + tx * 8;
        float4 o0, o1;
        o0.x = acc[i][0] + bz[0]; o0.y = acc[i][1] + bz[1];
        o0.z = acc[i][2] + bz[2]; o0.w = acc[i][3] + bz[3];
        o1.x = acc[i][4] + bz[4]; o1.y = acc[i][5] + bz[5];
        o1.z = acc[i][6] + bz[6]; o1.w = acc[i][7] + bz[7];
        if (RELU) {
            o0.x = fmaxf(o0.x, 0.f); o0.y = fmaxf(o0.y, 0.f);
            o0.z = fmaxf(o0.z, 0.f); o0.w = fmaxf(o0.w, 0.f);
            o1.x = fmaxf(o1.x, 0.f); o1.y = fmaxf(o1.y, 0.f);
            o1.z = fmaxf(o1.z, 0.f); o1.w = fmaxf(o1.w, 0.f);
        }
        *reinterpret_cast<float4*>(&C[gr]) = o0;
        *reinterpret_cast<float4*>(&C[gr + 4]) = o1;
    }
}

// small guarded GEMM for the N=30 head (B is (N,K) row-major, BT semantics)
#define BM 64
#define BN 64
#define BKK 16
template <bool BT, bool RELU>
__global__ void k_gemm(const float* __restrict__ A, const float* __restrict__ B,
                       const float* __restrict__ bias, float* __restrict__ C,
                       int M, int N, int K) {
    __shared__ __align__(16) float As[BKK][BM + 4];
    __shared__ __align__(16) float Bs[BKK][BN + 4];
    int bm = blockIdx.y * BM, bn = blockIdx.x * BN;
    int tid = threadIdx.x;
    int tx = tid & 15, ty = tid >> 4;
    float acc[4][4] = {};
    for (int k0 = 0; k0 < K; k0 += BKK) {
#pragma unroll
        for (int i = 0; i < 4; i++) {
            int idx = tid + i * 256;
            int r = idx >> 4, kk = idx & 15;
            int gr = bm + r;
            As[kk][r] = (gr < M) ? A[(size_t)gr * K + k0 + kk] : 0.f;
        }
#pragma unroll
        for (int i = 0; i < 4; i++) {
            int idx = tid + i * 256;
            if (!BT) {
                int kk = idx >> 6, n = idx & 63;
                int gn = bn + n;
                Bs[kk][n] = (gn < N) ? B[(size_t)(k0 + kk) * N + gn] : 0.f;
            } else {
                int n = idx >> 4, kk = idx & 15;
                int gn = bn + n;
                Bs[kk][n] = (gn < N) ? B[(size_t)gn * K + k0 + kk] : 0.f;
            }
        }
        __syncthreads();
#pragma unroll
        for (int kk = 0; kk < BKK; kk++) {
            float4 av = *reinterpret_cast<const float4*>(&As[kk][ty * 4]);
            float4 bv = *reinterpret_cast<const float4*>(&Bs[kk][tx * 4]);
            float a[4] = {av.x, av.y, av.z, av.w};
            float bb[4] = {bv.x, bv.y, bv.z, bv.w};
#pragma unroll
            for (int i = 0; i < 4; i++)
#pragma unroll
                for (int j = 0; j < 4; j++)
                    acc[i][j] += a[i] * bb[j];
        }
        __syncthreads();
    }
#pragma unroll
    for (int i = 0; i < 4; i++) {
        int gr = bm + ty * 4 + i;
        if (gr >= M) continue;
#pragma unroll
        for (int j = 0; j < 4; j++) {
            int gn = bn + tx * 4 + j;
            if (gn >= N) continue;
            float v = acc[i][j] + bias[gn];
            if (RELU) v = fmaxf(v, 0.f);
            C[(size_t)gr * N + gn] = v;
        }
    }
}

__global__ void k_split(const float* __restrict__ pred, float* __restrict__ out) {
    int row = blockIdx.x;
    int t = threadIdx.x;
    if (t < 6)
        out[(size_t)row * 6 + t] = pred[(size_t)row * 30 + t];
    else if (t < 30)
        out[(size_t)BSZ * NV * 6 + (size_t)row * 24 + (t - 6)] = pred[(size_t)row * 30 + t];
}

// ---------------- host ----------------
static inline int cdiv(int a, int b) { return (a + b - 1) / b; }

#define SYMF(p, s) do { void* _t; cudaGetSymbolAddress(&_t, s); p = (float*)_t; } while (0)
#define SYMI(p, s) do { void* _t; cudaGetSymbolAddress(&_t, s); p = (int*)_t; } while (0)

extern "C" void kernel_launch(void* const* d_in, const int* in_sizes, int n_in,
                              void* d_out, int out_size) {
    const float* vertices = (const float*)d_in[0];
    const float* onehot   = (const float*)d_in[1];
    const float* dir0 = (const float*)d_in[2];
    const float* w1   = (const float*)d_in[3];
    const float* b1   = (const float*)d_in[4];
    const float* dir1 = (const float*)d_in[5];
    const float* w2   = (const float*)d_in[6];
    const float* b2   = (const float*)d_in[7];
    const float* dir2 = (const float*)d_in[8];
    const float* w3   = (const float*)d_in[9];
    const float* b3   = (const float*)d_in[10];
    const float* dir3 = (const float*)d_in[11];
    const float* w4   = (const float*)d_in[12];
    const float* b4   = (const float*)d_in[13];
    const float* dir4 = (const float*)d_in[14];
    const float* g_bn1 = (const float*)d_in[15];
    const float* be_bn1 = (const float*)d_in[16];
    const float* g_bn2 = (const float*)d_in[17];
    const float* be_bn2 = (const float*)d_in[18];
    const float* g_bn3 = (const float*)d_in[19];
    const float* be_bn3 = (const float*)d_in[20];
    const float* wc1 = (const float*)d_in[21];
    const float* bc1 = (const float*)d_in[22];
    const float* wc2 = (const float*)d_in[23];
    const float* bc2 = (const float*)d_in[24];
    const float* wc3 = (const float*)d_in[25];
    const float* bc3 = (const float*)d_in[26];
    float* out = (float*)d_out;

    float *p_d0, *p_d1, *p_d2, *p_d3, *p_d4;
    SYMF(p_d0, g_d0); SYMF(p_d1, g_d1); SYMF(p_d2, g_d2); SYMF(p_d3, g_d3); SYMF(p_d4, g_d4);
    int *p_nb, *p_nb1, *p_nb2, *p_nbp1, *p_nbp2, *p_n1, *p_n2;
    SYMI(p_nb, g_nb); SYMI(p_nb1, g_nb1); SYMI(p_nb2, g_nb2);
    SYMI(p_nbp1, g_nbp1); SYMI(p_nbp2, g_nbp2); SYMI(p_n1, g_n1); SYMI(p_n2, g_n2);
    float *p_fm0, *p_fo1, *p_cv1, *p_fm1, *p_fp1, *p_fo2, *p_cv2, *p_fm2;
    float *p_fo3, *p_cv3, *p_fm3, *p_fp2, *p_fo4, *p_fm4, *p_fg, *p_fuse, *p_h1, *p_h2, *p_pred;
    float *p_mean, *p_var;
    SYMF(p_fm0, g_fm0); SYMF(p_fo1, g_fo1); SYMF(p_cv1, g_cv1); SYMF(p_fm1, g_fm1);
    SYMF(p_fp1, g_fp1); SYMF(p_fo2, g_fo2); SYMF(p_cv2, g_cv2); SYMF(p_fm2, g_fm2);
    SYMF(p_fo3, g_fo3); SYMF(p_cv3, g_cv3); SYMF(p_fm3, g_fm3); SYMF(p_fp2, g_fp2);
    SYMF(p_fo4, g_fo4); SYMF(p_fm4, g_fm4); SYMF(p_fg, g_fg); SYMF(p_fuse, g_fuse);
    SYMF(p_h1, g_h1); SYMF(p_h2, g_h2); SYMF(p_pred, g_pred);
    SYMF(p_mean, g_mean); SYMF(p_var, g_var);

    // 0) normalize direction banks
    k_norm_dirs<<<cdiv(896, 256), 256>>>(dir0, p_d0, 896);
    k_norm_dirs<<<cdiv(896, 256), 256>>>(dir1, p_d1, 896);
    k_norm_dirs<<<cdiv(1792, 256), 256>>>(dir2, p_d2, 1792);
    k_norm_dirs<<<cdiv(1792, 256), 256>>>(dir3, p_d3, 1792);
    k_norm_dirs<<<cdiv(3584, 256), 256>>>(dir4, p_d4, 3584);

    // 1) kNN graphs
    k_knn<10><<<dim3(cdiv(NV, 128), BSZ), 128, NV * 3 * 4>>>(vertices, NV, NV, NV, p_nb);
    k_knn<4><<<dim3(cdiv(512, 128), BSZ), 128, NV * 3 * 4>>>(vertices, NV, NV, 512, p_nbp1);
    k_knn<10><<<dim3(cdiv(512, 128), BSZ), 128, 512 * 3 * 4>>>(vertices, NV, 512, 512, p_nb1);
    k_knn<4><<<dim3(1, BSZ), 128, 512 * 3 * 4>>>(vertices, NV, 512, 128, p_nbp2);
    k_knn<10><<<dim3(1, BSZ), 128, 128 * 3 * 4>>>(vertices, NV, 128, 128, p_nb2);

    // 2) conv_surface -> fm0
    k_conv_surface<<<dim3(NV, BSZ), 128>>>(vertices, p_nb, p_d0, p_fm0);

    // 3) layer1
    k_gemm_big<false, false><<<dim3(1024 / GBN, BSZ * NV / GBM), 256>>>(
        p_fm0, w1, b1, p_fo1, BSZ * NV, 1024, 128);
    k_conv_layer<<<dim3(NV, BSZ), 128>>>(vertices, NV, NV, p_nb, p_fo1, p_d1, 128, p_cv1);
    k_bn_stats<<<128 / 32, dim3(32, 8)>>>(p_cv1, BSZ * NV, 128, p_mean, p_var);
    k_bn_apply<<<cdiv(BSZ * NV * 128, 256), 256>>>(p_cv1, p_mean, p_var, g_bn1, be_bn1,
                                                   p_fm1, BSZ * NV * 128, 128);

    // 4) pool1
    k_pool<<<dim3(512, BSZ), 128>>>(p_fm1, NV, p_nbp1, 128, p_fp1);

    // 5) layer2
    k_gemm_big<false, false><<<dim3(2048 / GBN, BSZ * 512 / GBM), 256>>>(
        p_fp1, w2, b2, p_fo2, BSZ * 512, 2048, 128);
    k_conv_layer<<<dim3(512, BSZ), 256>>>(vertices, NV, 512, p_nb1, p_fo2, p_d2, 256, p_cv2);
    k_bn_stats<<<256 / 32, dim3(32, 8)>>>(p_cv2, BSZ * 512, 256, p_mean, p_var);
    k_bn_apply<<<cdiv(BSZ * 512 * 256, 256), 256>>>(p_cv2, p_mean, p_var, g_bn2, be_bn2,
                                                    p_fm2, BSZ * 512 * 256, 256);

    // 6) layer3
    k_gemm_big<false, false><<<dim3(2048 / GBN, BSZ * 512 / GBM), 256>>>(
        p_fm2, w3, b3, p_fo3, BSZ * 512, 2048, 256);
    k_conv_layer<<<dim3(512, BSZ), 256>>>(vertices, NV, 512, p_nb1, p_fo3, p_d3, 256, p_cv3);
    k_bn_stats<<<256 / 32, dim3(32, 8)>>>(p_cv3, BSZ * 512, 256, p_mean, p_var);
    k_bn_apply<<<cdiv(BSZ * 512 * 256, 256), 256>>>(p_cv3, p_mean, p_var, g_bn3, be_bn3,
                                                    p_fm3, BSZ * 512 * 256, 256);

    // 7) pool2
    k_pool<<<dim3(128, BSZ), 256>>>(p_fm3, 512, p_nbp2, 256, p_fp2);

    // 8) layer4
    k_gemm_big<false, false><<<dim3(4096 / GBN, BSZ * 128 / GBM), 256>>>(
        p_fp2, w4, b4, p_fo4, BSZ * 128, 4096, 256);
    k_conv_layer<<<dim3(128, BSZ), 512>>>(vertices, NV, 128, p_nb2, p_fo4, p_d4, 512, p_fm4);

    // 9) global max feature
    k_fglobal<<<BSZ, 512>>>(p_fm4, p_fg);

    // 10) nearest indices
    k_nearest<<<dim3(cdiv(NV, 128), BSZ), 128, 512 * 3 * 4>>>(vertices, NV, NV, 512, p_n1);
    k_nearest<<<dim3(cdiv(NV, 128), BSZ), 128, 128 * 3 * 4>>>(vertices, NV, NV, 128, p_n2);

    // 11) assemble fuse + feat
    float* feat_out = out + (size_t)BSZ * NV * 6 + (size_t)BSZ * NV * 24;
    k_assemble<<<dim3(NV, BSZ), 256>>>(p_fm0, p_fm1, p_fm2, p_fm3, p_fm4, p_fg, onehot,
                                       p_n1, p_n2, p_fuse, feat_out);

    // 12) final MLP
    k_gemm_big<true, true><<<dim3(512 / GBN, BSZ * NV / GBM), 256>>>(
        p_fuse, wc1, bc1, p_h1, BSZ * NV, 512, 1808);
    k_gemm_big<true, true><<<dim3(512 / GBN, BSZ * NV / GBM), 256>>>(
        p_h1, wc2, bc2, p_h2, BSZ * NV, 512, 512);
    k_gemm<true, false><<<dim3(cdiv(30, BN), cdiv(BSZ * NV, BM)), 256>>>(
        p_h2, wc3, bc3, p_pred, BSZ * NV, 30, 512);

    // 13) split
    k_split<<<BSZ * NV, 32>>>(p_pred, out);
}

// round 4
// speedup vs baseline: 1.2171x; 1.0798x over previous
#include <cuda_runtime.h>
#include <math.h>

// ---------------- problem constants ----------------
#define BSZ 4
#define NV  2048

// ---------------- device scratch ----------------
__device__ float g_d0[3*896];
__device__ float g_d1[3*896];
__device__ float g_d2[3*1792];
__device__ float g_d3[3*1792];
__device__ float g_d4[3*3584];

__device__ int   g_nb  [BSZ*NV*10];
__device__ int   g_nb1 [BSZ*512*10];
__device__ int   g_nb2 [BSZ*128*10];
__device__ int   g_nbp1[BSZ*512*4];
__device__ int   g_nbp2[BSZ*128*4];
__device__ int   g_n1  [BSZ*NV];
__device__ int   g_n2  [BSZ*NV];

__device__ float g_fm0[BSZ*NV*128];
__device__ float g_fo1[BSZ*NV*1024];
__device__ float g_cv1[BSZ*NV*128];
__device__ float g_fm1[BSZ*NV*128];
__device__ float g_fp1[BSZ*512*128];
__device__ float g_fo2[BSZ*512*2048];
__device__ float g_cv2[BSZ*512*256];
__device__ float g_fm2[BSZ*512*256];
__device__ float g_fo3[BSZ*512*2048];
__device__ float g_cv3[BSZ*512*256];
__device__ float g_fm3[BSZ*512*256];
__device__ float g_fp2[BSZ*128*256];
__device__ float g_fo4[BSZ*128*4096];
__device__ float g_fm4[BSZ*128*512];
__device__ float g_fg [BSZ*512];
// decomposition buffers
__device__ float g_f01[BSZ*NV*256];
__device__ float g_f23[BSZ*512*512];
__device__ float g_pA [BSZ*NV*512];
__device__ float g_pB [BSZ*512*512];
__device__ float g_pC [BSZ*128*512];
__device__ float g_pDE[BSZ*512];
__device__ float g_h1 [BSZ*NV*512];
__device__ float g_h2 [BSZ*NV*512];
__device__ float g_pred[BSZ*NV*30];
__device__ float g_mean[256];
__device__ float g_var [256];

// ---------------- kernels ----------------

__global__ void k_norm_dirs(const float* __restrict__ dir, float* __restrict__ out, int D) {
    int c = blockIdx.x * blockDim.x + threadIdx.x;
    if (c >= D) return;
    float x = dir[c], y = dir[D + c], z = dir[2 * D + c];
    float n = fmaxf(sqrtf(x * x + y * y + z * z), 1e-12f);
    float inv = 1.f / n;
    out[c] = x * inv; out[D + c] = y * inv; out[2 * D + c] = z * inv;
}

template <int KN>
__global__ void k_knn(const float* __restrict__ pts, int bstride, int N, int Q,
                      int* __restrict__ out) {
    extern __shared__ float sp[];
    int b = blockIdx.y;
    const float* P = pts + (size_t)b * bstride * 3;
    for (int i = threadIdx.x; i < N * 3; i += blockDim.x) sp[i] = P[i];
    __syncthreads();
    int q = blockIdx.x * blockDim.x + threadIdx.x;
    if (q >= Q) return;
    float qx = sp[q * 3], qy = sp[q * 3 + 1], qz = sp[q * 3 + 2];
    float bd[KN]; int bi[KN];
#pragma unroll
    for (int i = 0; i < KN; i++) { bd[i] = 3.4e38f; bi[i] = 0; }
    for (int j = 0; j < N; j++) {
        if (j == q) continue;
        float dx = sp[j * 3] - qx, dy = sp[j * 3 + 1] - qy, dz = sp[j * 3 + 2] - qz;
        float d = dx * dx + dy * dy + dz * dz;
        if (d < bd[KN - 1]) {
            bd[KN - 1] = d; bi[KN - 1] = j;
#pragma unroll
            for (int r = KN - 1; r > 0; --r) {
                if (bd[r] < bd[r - 1]) {
                    float td = bd[r]; bd[r] = bd[r - 1]; bd[r - 1] = td;
                    int ti = bi[r]; bi[r] = bi[r - 1]; bi[r - 1] = ti;
                }
            }
        }
    }
    int* o = out + ((size_t)b * Q + q) * KN;
#pragma unroll
    for (int i = 0; i < KN; i++) o[i] = bi[i];
}

__global__ void k_nearest(const float* __restrict__ pts, int bstride, int Nt, int Ns,
                          int* __restrict__ out) {
    extern __shared__ float sp[];
    int b = blockIdx.y;
    const float* P = pts + (size_t)b * bstride * 3;
    for (int i = threadIdx.x; i < Ns * 3; i += blockDim.x) sp[i] = P[i];
    __syncthreads();
    int t = blockIdx.x * blockDim.x + threadIdx.x;
    if (t >= Nt) return;
    const float* T = pts + ((size_t)b * bstride + t) * 3;
    float qx = T[0], qy = T[1], qz = T[2];
    float best = 3.4e38f; int bi = 0;
    for (int j = 0; j < Ns; j++) {
        float dx = sp[j * 3] - qx, dy = sp[j * 3 + 1] - qy, dz = sp[j * 3 + 2] - qz;
        float d = dx * dx + dy * dy + dz * dz;
        if (d < best) { best = d; bi = j; }
    }
    out[(size_t)b * Nt + t] = bi;
}

// conv_surface -> writes fm0 AND f01[:, 0:128]
__global__ void k_conv_surface(const float* __restrict__ verts, const int* __restrict__ nb,
                               const float* __restrict__ sd, float* __restrict__ out,
                               float* __restrict__ f01) {
    int b = blockIdx.y, v = blockIdx.x;
    __shared__ float nd[10][3];
    size_t row = (size_t)b * NV + v;
    if (threadIdx.x < 10) {
        int j = nb[row * 10 + threadIdx.x];
        const float* c0 = verts + row * 3;
        const float* c1 = verts + ((size_t)b * NV + j) * 3;
        float dx = c1[0] - c0[0], dy = c1[1] - c0[1], dz = c1[2] - c0[2];
        float inv = 1.f / fmaxf(sqrtf(dx * dx + dy * dy + dz * dz), 1e-12f);
        nd[threadIdx.x][0] = dx * inv; nd[threadIdx.x][1] = dy * inv; nd[threadIdx.x][2] = dz * inv;
    }
    __syncthreads();
    int c = threadIdx.x;
    float acc = 0.f;
#pragma unroll
    for (int s = 0; s < 7; s++) {
        int col = s * 128 + c;
        float sx = sd[col], sy = sd[896 + col], sz = sd[1792 + col];
        float m = 0.f;
#pragma unroll
        for (int n = 0; n < 10; n++) {
            float t = nd[n][0] * sx + nd[n][1] * sy + nd[n][2] * sz;
            m = fmaxf(m, t);
        }
        acc += m;
    }
    float r = fmaxf(acc, 0.f);
    out[row * 128 + c] = r;
    f01[row * 256 + c] = r;
}

__global__ void k_conv_layer(const float* __restrict__ verts, int vstride, int V,
                             const int* __restrict__ nb, const float* __restrict__ fo,
                             const float* __restrict__ sd, int OC, float* __restrict__ out) {
    int b = blockIdx.y, v = blockIdx.x;
    __shared__ float nd[10][3];
    __shared__ int nidx[10];
    if (threadIdx.x < 10) {
        int j = nb[((size_t)b * V + v) * 10 + threadIdx.x];
        nidx[threadIdx.x] = j;
        const float* c0 = verts + ((size_t)b * vstride + v) * 3;
        const float* c1 = verts + ((size_t)b * vstride + j) * 3;
        float dx = c1[0] - c0[0], dy = c1[1] - c0[1], dz = c1[2] - c0[2];
        float inv = 1.f / fmaxf(sqrtf(dx * dx + dy * dy + dz * dz), 1e-12f);
        nd[threadIdx.x][0] = dx * inv; nd[threadIdx.x][1] = dy * inv; nd[threadIdx.x][2] = dz * inv;
    }
    __syncthreads();
    int c = threadIdx.x;
    int FW = 8 * OC, D = 7 * OC;
    const float* base = fo + (size_t)b * V * FW;
    float acc = base[(size_t)v * FW + c];
#pragma unroll
    for (int s = 0; s < 7; s++) {
        int col = s * OC + c;
        float sx = sd[col], sy = sd[D + col], sz = sd[2 * D + col];
        float m = -3.4e38f;
#pragma unroll
        for (int n = 0; n < 10; n++) {
            float t = fmaxf(nd[n][0] * sx + nd[n][1] * sy + nd[n][2] * sz, 0.f);
            float sup = base[(size_t)nidx[n] * FW + OC + col];
            m = fmaxf(m, t * sup);
        }
        acc += m;
    }
    out[((size_t)b * V + v) * OC + c] = acc;
}

__global__ void k_bn_stats(const float* __restrict__ x, int R, int C,
                           float* __restrict__ mean, float* __restrict__ var) {
    int c = blockIdx.x * 32 + threadIdx.x;
    float s = 0.f, s2 = 0.f;
    for (int r = threadIdx.y; r < R; r += 8) {
        float v = x[(size_t)r * C + c];
        s += v; s2 += v * v;
    }
    __shared__ float sh[8][32], sh2[8][32];
    sh[threadIdx.y][threadIdx.x] = s; sh2[threadIdx.y][threadIdx.x] = s2;
    __syncthreads();
    if (threadIdx.y == 0) {
        float ts = 0.f, ts2 = 0.f;
#pragma unroll
        for (int y = 0; y < 8; y++) { ts += sh[y][threadIdx.x]; ts2 += sh2[y][threadIdx.x]; }
        float m = ts / (float)R;
        mean[c] = m;
        var[c] = ts2 / (float)R - m * m;
    }
}

// y (stride Cy, offset coff) = relu(bn(x)); optionally also writes y2 (dense C)
__global__ void k_bn_apply(const float* __restrict__ x, const float* __restrict__ mean,
                           const float* __restrict__ var, const float* __restrict__ g,
                           const float* __restrict__ be, float* __restrict__ y,
                           int total, int C, int Cy, int coff,
                           float* __restrict__ y2) {
    int i = blockIdx.x * blockDim.x + threadIdx.x;
    if (i >= total) return;
    int c = i % C;
    int r = i / C;
    float v = (x[i] - mean[c]) * rsqrtf(var[c] + 1e-5f) * g[c] + be[c];
    v = fmaxf(v, 0.f);
    y[(size_t)r * Cy + coff + c] = v;
    if (y2) y2[i] = v;
}

__global__ void k_pool(const float* __restrict__ fm, int Vin, const int* __restrict__ nbp,
                       int C, float* __restrict__ out) {
    int b = blockIdx.y, p = blockIdx.x, c = threadIdx.x;
    int P = gridDim.x;
    const int* nr = nbp + ((size_t)b * P + p) * 4;
    float m = -3.4e38f;
#pragma unroll
    for (int j = 0; j < 4; j++)
        m = fmaxf(m, fm[((size_t)b * Vin + nr[j]) * C + c]);
    out[((size_t)b * P + p) * C + c] = m;
}

__global__ void k_fglobal(const float* __restrict__ fm4, float* __restrict__ fg) {
    int b = blockIdx.x, c = threadIdx.x;
    float m = -3.4e38f;
    for (int r = 0; r < 128; r++)
        m = fmaxf(m, fm4[((size_t)b * 128 + r) * 512 + c]);
    fg[b * 512 + c] = m;
}

// feat (1296) -> d_out only (fuse no longer materialized)
__global__ void k_assemble(const float* __restrict__ fm0, const float* __restrict__ fm1,
                           const float* __restrict__ fm2, const float* __restrict__ fm3,
                           const float* __restrict__ fm4, const float* __restrict__ onehot,
                           const int* __restrict__ n1, const int* __restrict__ n2,
                           float* __restrict__ feat) {
    int b = blockIdx.y, v = blockIdx.x;
    size_t row = (size_t)b * NV + v;
    int i1 = n1[row], i2 = n2[row];
    float* fe = feat + row * 1296;
    for (int c = threadIdx.x; c < 1296; c += blockDim.x) {
        float val;
        if (c < 128)        val = fm0[row * 128 + c];
        else if (c < 256)   val = fm1[row * 128 + (c - 128)];
        else if (c < 512)   val = fm2[((size_t)b * 512 + i1) * 256 + (c - 256)];
        else if (c < 768)   val = fm3[((size_t)b * 512 + i1) * 256 + (c - 512)];
        else if (c < 1280)  val = fm4[((size_t)b * 128 + i2) * 512 + (c - 768)];
        else                val = onehot[b * 16 + (c - 1280)];
        fe[c] = val;
    }
}

// pDE[b,o] = bc1[o] + fg[b]·wc1[o,1280:1792] + oh[b]·wc1[o,1792:1808]
__global__ void k_pde(const float* __restrict__ fg, const float* __restrict__ onehot,
                      const float* __restrict__ wc1, const float* __restrict__ bc1,
                      float* __restrict__ pde) {
    int b = blockIdx.x, o = threadIdx.x;
    const float* w = wc1 + (size_t)o * 1808;
    float s = bc1[o];
    for (int c = 0; c < 512; c++) s = fmaf(fg[b * 512 + c], w[1280 + c], s);
#pragma unroll
    for (int j = 0; j < 16; j++) s = fmaf(onehot[b * 16 + j], w[1792 + j], s);
    pde[b * 512 + o] = s;
}

// h1[row] = relu(pA[row] + pB[b,n1] + pC[b,n2] + pDE[b])
__global__ void k_combine(const float* __restrict__ pA, const float* __restrict__ pB,
                          const float* __restrict__ pC, const float* __restrict__ pDE,
                          const int* __restrict__ n1, const int* __restrict__ n2,
                          float* __restrict__ h1) {
    int row = blockIdx.x;
    int b = row >> 11;
    int i1 = n1[row], i2 = n2[row];
    const float4* a  = (const float4*)(pA + (size_t)row * 512);
    const float4* pb = (const float4*)(pB + ((size_t)b * 512 + i1) * 512);
    const float4* pc = (const float4*)(pC + ((size_t)b * 128 + i2) * 512);
    const float4* pd = (const float4*)(pDE + (size_t)b * 512);
    float4* o = (float4*)(h1 + (size_t)row * 512);
    for (int c = threadIdx.x; c < 128; c += blockDim.x) {
        float4 va = a[c], vb = pb[c], vc = pc[c], vd = pd[c];
        float4 r;
        r.x = fmaxf(va.x + vb.x + vc.x + vd.x, 0.f);
        r.y = fmaxf(va.y + vb.y + vc.y + vd.y, 0.f);
        r.z = fmaxf(va.z + vb.z + vc.z + vd.z, 0.f);
        r.w = fmaxf(va.w + vb.w + vc.w + vd.w, 0.f);
        o[c] = r;
    }
}

// ---------------- big SGEMM: 128x128 tile, BK=8, 8x8 microtile, double buffered ----
// Requires M%128==0, N%128==0, K%8==0.
// BT: B is (N,K) row-major with row stride ldb. !BT: B is (K,N) with row stride ldb.
#define GBM 128
#define GBN 128
#define GBK 8
template <bool BT, bool RELU, bool BIAS>
__global__ void __launch_bounds__(256)
k_gemm_big(const float* __restrict__ A, const float* __restrict__ B,
           const float* __restrict__ bias, float* __restrict__ C,
           int M, int N, int K, int ldb) {
    __shared__ __align__(16) float As[2][GBK][GBM];
    __shared__ __align__(16) float Bs[2][GBK][GBN];
    int bm = blockIdx.y * GBM, bn = blockIdx.x * GBN;
    int tid = threadIdx.x;
    int tx = tid & 15, ty = tid >> 4;

    int a_r = tid >> 1;
    int a_c = (tid & 1) * 4;
    int b_r = tid >> 5;
    int b_c = (tid & 31) * 4;

    const float* Arow = A + (size_t)(bm + a_r) * K + a_c;
    const float* Brow_t = BT ? (B + (size_t)(bn + a_r) * ldb + a_c) : nullptr;
    const float* Brow_n = BT ? nullptr : (B + (size_t)b_r * ldb + bn + b_c);

    float4 areg = *reinterpret_cast<const float4*>(Arow);
    float4 breg = BT ? *reinterpret_cast<const float4*>(Brow_t)
                     : *reinterpret_cast<const float4*>(Brow_n);

    As[0][a_c + 0][a_r] = areg.x; As[0][a_c + 1][a_r] = areg.y;
    As[0][a_c + 2][a_r] = areg.z; As[0][a_c + 3][a_r] = areg.w;
    if (BT) {
        Bs[0][a_c + 0][a_r] = breg.x; Bs[0][a_c + 1][a_r] = breg.y;
        Bs[0][a_c + 2][a_r] = breg.z; Bs[0][a_c + 3][a_r] = breg.w;
    } else {
        *reinterpret_cast<float4*>(&Bs[0][b_r][b_c]) = breg;
    }
    __syncthreads();

    float acc[8][8] = {};
    int nT = K / GBK;
    for (int t = 0; t < nT; t++) {
        int buf = t & 1;
        if (t + 1 < nT) {
            int k0 = (t + 1) * GBK;
            areg = *reinterpret_cast<const float4*>(Arow + k0);
            breg = BT ? *reinterpret_cast<const float4*>(Brow_t + k0)
                      : *reinterpret_cast<const float4*>(Brow_n + (size_t)k0 * ldb);
        }
#pragma unroll
        for (int kk = 0; kk < GBK; kk++) {
            float4 av0 = *reinterpret_cast<const float4*>(&As[buf][kk][ty * 8]);
            float4 av1 = *reinterpret_cast<const float4*>(&As[buf][kk][ty * 8 + 4]);
            float4 bv0 = *reinterpret_cast<const float4*>(&Bs[buf][kk][tx * 8]);
            float4 bv1 = *reinterpret_cast<const float4*>(&Bs[buf][kk][tx * 8 + 4]);
            float ar[8] = {av0.x, av0.y, av0.z, av0.w, av1.x, av1.y, av1.z, av1.w};
            float br[8] = {bv0.x, bv0.y, bv0.z, bv0.w, bv1.x, bv1.y, bv1.z, bv1.w};
#pragma unroll
            for (int i = 0; i < 8; i++)
#pragma unroll
                for (int j = 0; j < 8; j++)
                    acc[i][j] = fmaf(ar[i], br[j], acc[i][j]);
        }
        if (t + 1 < nT) {
            int nb = (t + 1) & 1;
            As[nb][a_c + 0][a_r] = areg.x; As[nb][a_c + 1][a_r] = areg.y;
            As[nb][a_c + 2][a_r] = areg.z; As[nb][a_c + 3][a_r] = areg.w;
            if (BT) {
                Bs[nb][a_c + 0][a_r] = breg.x; Bs[nb][a_c + 1][a_r] = breg.y;
                Bs[nb][a_c + 2][a_r] = breg.z; Bs[nb][a_c + 3][a_r] = breg.w;
            } else {
                *reinterpret_cast<float4*>(&Bs[nb][b_r][b_c]) = breg;
            }
            __syncthreads();
        }
    }

    float bz[8];
#pragma unroll
    for (int j = 0; j < 8; j++) bz[j] = BIAS ? bias[bn + tx * 8 + j] : 0.f;
#pragma unroll
    for (int i = 0; i < 8; i++) {
        size_t gr = (size_t)(bm + ty * 8 + i) * N + bn + tx * 8;
        float4 o0, o1;
        o0.x = acc[i][0] + bz[0]; o0.y = acc[i][1] + bz[1];
        o0.z = acc[i][2] + bz[2]; o0.w = acc[i][3] + bz[3];
        o1.x = acc[i][4] + bz[4]; o1.y = acc[i][5] + bz[5];
        o1.z = acc[i][6] + bz[6]; o1.w = acc[i][7] + bz[7];
        if (RELU) {
            o0.x = fmaxf(o0.x, 0.f); o0.y = fmaxf(o0.y, 0.f);
            o0.z = fmaxf(o0.z, 0.f); o0.w = fmaxf(o0.w, 0.f);
            o1.x = fmaxf(o1.x, 0.f); o1.y = fmaxf(o1.y, 0.f);
            o1.z = fmaxf(o1.z, 0.f); o1.w = fmaxf(o1.w, 0.f);
        }
        *reinterpret_cast<float4*>(&C[gr]) = o0;
        *reinterpret_cast<float4*>(&C[gr + 4]) = o1;
    }
}

// small guarded GEMM for the N=30 head (B is (N,K) row-major)
#define BM 64
#define BN 64
#define BKK 16
template <bool BT, bool RELU>
__global__ void k_gemm(const float* __restrict__ A, const float* __restrict__ B,
                       const float* __restrict__ bias, float* __restrict__ C,
                       int M, int N, int K) {
    __shared__ __align__(16) float As[BKK][BM + 4];
    __shared__ __align__(16) float Bs[BKK][BN + 4];
    int bm = blockIdx.y * BM, bn = blockIdx.x * BN;
    int tid = threadIdx.x;
    int tx = tid & 15, ty = tid >> 4;
    float acc[4][4] = {};
    for (int k0 = 0; k0 < K; k0 += BKK) {
#pragma unroll
        for (int i = 0; i < 4; i++) {
            int idx = tid + i * 256;
            int r = idx >> 4, kk = idx & 15;
            int gr = bm + r;
            As[kk][r] = (gr < M) ? A[(size_t)gr * K + k0 + kk] : 0.f;
        }
#pragma unroll
        for (int i = 0; i < 4; i++) {
            int idx = tid + i * 256;
            if (!BT) {
                int kk = idx >> 6, n = idx & 63;
                int gn = bn + n;
                Bs[kk][n] = (gn < N) ? B[(size_t)(k0 + kk) * N + gn] : 0.f;
            } else {
                int n = idx >> 4, kk = idx & 15;
                int gn = bn + n;
                Bs[kk][n] = (gn < N) ? B[(size_t)gn * K + k0 + kk] : 0.f;
            }
        }
        __syncthreads();
#pragma unroll
        for (int kk = 0; kk < BKK; kk++) {
            float4 av = *reinterpret_cast<const float4*>(&As[kk][ty * 4]);
            float4 bv = *reinterpret_cast<const float4*>(&Bs[kk][tx * 4]);
            float a[4] = {av.x, av.y, av.z, av.w};
            float bb[4] = {bv.x, bv.y, bv.z, bv.w};
#pragma unroll
            for (int i = 0; i < 4; i++)
#pragma unroll
                for (int j = 0; j < 4; j++)
                    acc[i][j] += a[i] * bb[j];
        }
        __syncthreads();
    }
#pragma unroll
    for (int i = 0; i < 4; i++) {
        int gr = bm + ty * 4 + i;
        if (gr >= M) continue;
#pragma unroll
        for (int j = 0; j < 4; j++) {
            int gn = bn + tx * 4 + j;
            if (gn >= N) continue;
            float v = acc[i][j] + bias[gn];
            if (RELU) v = fmaxf(v, 0.f);
            C[(size_t)gr * N + gn] = v;
        }
    }
}

__global__ void k_split(const float* __restrict__ pred, float* __restrict__ out) {
    int row = blockIdx.x;
    int t = threadIdx.x;
    if (t < 6)
        out[(size_t)row * 6 + t] = pred[(size_t)row * 30 + t];
    else if (t < 30)
        out[(size_t)BSZ * NV * 6 + (size_t)row * 24 + (t - 6)] = pred[(size_t)row * 30 + t];
}

// ---------------- host ----------------
static inline int cdiv(int a, int b) { return (a + b - 1) / b; }

#define SYMF(p, s) do { void* _t; cudaGetSymbolAddress(&_t, s); p = (float*)_t; } while (0)
#define SYMI(p, s) do { void* _t; cudaGetSymbolAddress(&_t, s); p = (int*)_t; } while (0)

extern "C" void kernel_launch(void* const* d_in, const int* in_sizes, int n_in,
                              void* d_out, int out_size) {
    const float* vertices = (const float*)d_in[0];
    const float* onehot   = (const float*)d_in[1];
    const float* dir0 = (const float*)d_in[2];
    const float* w1   = (const float*)d_in[3];
    const float* b1   = (const float*)d_in[4];
    const float* dir1 = (const float*)d_in[5];
    const float* w2   = (const float*)d_in[6];
    const float* b2   = (const float*)d_in[7];
    const float* dir2 = (const float*)d_in[8];
    const float* w3   = (const float*)d_in[9];
    const float* b3   = (const float*)d_in[10];
    const float* dir3 = (const float*)d_in[11];
    const float* w4   = (const float*)d_in[12];
    const float* b4   = (const float*)d_in[13];
    const float* dir4 = (const float*)d_in[14];
    const float* g_bn1 = (const float*)d_in[15];
    const float* be_bn1 = (const float*)d_in[16];
    const float* g_bn2 = (const float*)d_in[17];
    const float* be_bn2 = (const float*)d_in[18];
    const float* g_bn3 = (const float*)d_in[19];
    const float* be_bn3 = (const float*)d_in[20];
    const float* wc1 = (const float*)d_in[21];
    const float* bc1 = (const float*)d_in[22];
    const float* wc2 = (const float*)d_in[23];
    const float* bc2 = (const float*)d_in[24];
    const float* wc3 = (const float*)d_in[25];
    const float* bc3 = (const float*)d_in[26];
    float* out = (float*)d_out;

    float *p_d0, *p_d1, *p_d2, *p_d3, *p_d4;
    SYMF(p_d0, g_d0); SYMF(p_d1, g_d1); SYMF(p_d2, g_d2); SYMF(p_d3, g_d3); SYMF(p_d4, g_d4);
    int *p_nb, *p_nb1, *p_nb2, *p_nbp1, *p_nbp2, *p_n1, *p_n2;
    SYMI(p_nb, g_nb); SYMI(p_nb1, g_nb1); SYMI(p_nb2, g_nb2);
    SYMI(p_nbp1, g_nbp1); SYMI(p_nbp2, g_nbp2); SYMI(p_n1, g_n1); SYMI(p_n2, g_n2);
    float *p_fm0, *p_fo1, *p_cv1, *p_fm1, *p_fp1, *p_fo2, *p_cv2, *p_fm2;
    float *p_fo3, *p_cv3, *p_fm3, *p_fp2, *p_fo4, *p_fm4, *p_fg;
    float *p_f01, *p_f23, *p_pA, *p_pB, *p_pC, *p_pDE;
    float *p_h1, *p_h2, *p_pred, *p_mean, *p_var;
    SYMF(p_fm0, g_fm0); SYMF(p_fo1, g_fo1); SYMF(p_cv1, g_cv1); SYMF(p_fm1, g_fm1);
    SYMF(p_fp1, g_fp1); SYMF(p_fo2, g_fo2); SYMF(p_cv2, g_cv2); SYMF(p_fm2, g_fm2);
    SYMF(p_fo3, g_fo3); SYMF(p_cv3, g_cv3); SYMF(p_fm3, g_fm3); SYMF(p_fp2, g_fp2);
    SYMF(p_fo4, g_fo4); SYMF(p_fm4, g_fm4); SYMF(p_fg, g_fg);
    SYMF(p_f01, g_f01); SYMF(p_f23, g_f23); SYMF(p_pA, g_pA); SYMF(p_pB, g_pB);
    SYMF(p_pC, g_pC); SYMF(p_pDE, g_pDE);
    SYMF(p_h1, g_h1); SYMF(p_h2, g_h2); SYMF(p_pred, g_pred);
    SYMF(p_mean, g_mean); SYMF(p_var, g_var);

    // 0) normalize direction banks
    k_norm_dirs<<<cdiv(896, 256), 256>>>(dir0, p_d0, 896);
    k_norm_dirs<<<cdiv(896, 256), 256>>>(dir1, p_d1, 896);
    k_norm_dirs<<<cdiv(1792, 256), 256>>>(dir2, p_d2, 1792);
    k_norm_dirs<<<cdiv(1792, 256), 256>>>(dir3, p_d3, 1792);
    k_norm_dirs<<<cdiv(3584, 256), 256>>>(dir4, p_d4, 3584);

    // 1) kNN graphs
    k_knn<10><<<dim3(cdiv(NV, 128), BSZ), 128, NV * 3 * 4>>>(vertices, NV, NV, NV, p_nb);
    k_knn<4><<<dim3(cdiv(512, 128), BSZ), 128, NV * 3 * 4>>>(vertices, NV, NV, 512, p_nbp1);
    k_knn<10><<<dim3(cdiv(512, 128), BSZ), 128, 512 * 3 * 4>>>(vertices, NV, 512, 512, p_nb1);
    k_knn<4><<<dim3(1, BSZ), 128, 512 * 3 * 4>>>(vertices, NV, 512, 128, p_nbp2);
    k_knn<10><<<dim3(1, BSZ), 128, 128 * 3 * 4>>>(vertices, NV, 128, 128, p_nb2);

    // 2) conv_surface -> fm0 (+ f01 cols 0:128)
    k_conv_surface<<<dim3(NV, BSZ), 128>>>(vertices, p_nb, p_d0, p_fm0, p_f01);

    // 3) layer1: fm1 -> f01 cols 128:256 (+ dense fm1 for pooling/feat)
    k_gemm_big<false, false, true><<<dim3(1024 / GBN, BSZ * NV / GBM), 256>>>(
        p_fm0, w1, b1, p_fo1, BSZ * NV, 1024, 128, 1024);
    k_conv_layer<<<dim3(NV, BSZ), 128>>>(vertices, NV, NV, p_nb, p_fo1, p_d1, 128, p_cv1);
    k_bn_stats<<<128 / 32, dim3(32, 8)>>>(p_cv1, BSZ * NV, 128, p_mean, p_var);
    k_bn_apply<<<cdiv(BSZ * NV * 128, 256), 256>>>(p_cv1, p_mean, p_var, g_bn1, be_bn1,
                                                   p_f01, BSZ * NV * 128, 128, 256, 128, p_fm1);

    // 4) pool1
    k_pool<<<dim3(512, BSZ), 128>>>(p_fm1, NV, p_nbp1, 128, p_fp1);

    // 5) layer2: fm2 -> f23 cols 0:256 (+ dense fm2)
    k_gemm_big<false, false, true><<<dim3(2048 / GBN, BSZ * 512 / GBM), 256>>>(
        p_fp1, w2, b2, p_fo2, BSZ * 512, 2048, 128, 2048);
    k_conv_layer<<<dim3(512, BSZ), 256>>>(vertices, NV, 512, p_nb1, p_fo2, p_d2, 256, p_cv2);
    k_bn_stats<<<256 / 32, dim3(32, 8)>>>(p_cv2, BSZ * 512, 256, p_mean, p_var);
    k_bn_apply<<<cdiv(BSZ * 512 * 256, 256), 256>>>(p_cv2, p_mean, p_var, g_bn2, be_bn2,
                                                    p_f23, BSZ * 512 * 256, 256, 512, 0, p_fm2);

    // 6) layer3: fm3 -> f23 cols 256:512 (+ dense fm3)
    k_gemm_big<false, false, true><<<dim3(2048 / GBN, BSZ * 512 / GBM), 256>>>(
        p_fm2, w3, b3, p_fo3, BSZ * 512, 2048, 256, 2048);
    k_conv_layer<<<dim3(512, BSZ), 256>>>(vertices, NV, 512, p_nb1, p_fo3, p_d3, 256, p_cv3);
    k_bn_stats<<<256 / 32, dim3(32, 8)>>>(p_cv3, BSZ * 512, 256, p_mean, p_var);
    k_bn_apply<<<cdiv(BSZ * 512 * 256, 256), 256>>>(p_cv3, p_mean, p_var, g_bn3, be_bn3,
                                                    p_f23, BSZ * 512 * 256, 256, 512, 256, p_fm3);

    // 7) pool2
    k_pool<<<dim3(128, BSZ), 256>>>(p_fm3, 512, p_nbp2, 256, p_fp2);

    // 8) layer4
    k_gemm_big<false, false, true><<<dim3(4096 / GBN, BSZ * 128 / GBM), 256>>>(
        p_fp2, w4, b4, p_fo4, BSZ * 128, 4096, 256, 4096);
    k_conv_layer<<<dim3(128, BSZ), 512>>>(vertices, NV, 128, p_nb2, p_fo4, p_d4, 512, p_fm4);

    // 9) global max feature
    k_fglobal<<<BSZ, 512>>>(p_fm4, p_fg);

    // 10) nearest indices
    k_nearest<<<dim3(cdiv(NV, 128), BSZ), 128, 512 * 3 * 4>>>(vertices, NV, NV, 512, p_n1);
    k_nearest<<<dim3(cdiv(NV, 128), BSZ), 128, 128 * 3 * 4>>>(vertices, NV, NV, 128, p_n2);

    // 11) feat -> d_out
    float* feat_out = out + (size_t)BSZ * NV * 6 + (size_t)BSZ * NV * 24;
    k_assemble<<<dim3(NV, BSZ), 256>>>(p_fm0, p_fm1, p_fm2, p_fm3, p_fm4, onehot,
                                       p_n1, p_n2, feat_out);

    // 12) decomposed fuse layer: pA/pB/pC partial GEMMs + pDE + combine
    k_gemm_big<true, false, false><<<dim3(512 / GBN, BSZ * NV / GBM), 256>>>(
        p_f01, wc1, nullptr, p_pA, BSZ * NV, 512, 256, 1808);
    k_gemm_big<true, false, false><<<dim3(512 / GBN, BSZ * 512 / GBM), 256>>>(
        p_f23, wc1 + 256, nullptr, p_pB, BSZ * 512, 512, 512, 1808);
    k_gemm_big<true, false, false><<<dim3(512 / GBN, BSZ * 128 / GBM), 256>>>(
        p_fm4, wc1 + 768, nullptr, p_pC, BSZ * 128, 512, 512, 1808);
    k_pde<<<BSZ, 512>>>(p_fg, onehot, wc1, bc1, p_pDE);
    k_combine<<<BSZ * NV, 128>>>(p_pA, p_pB, p_pC, p_pDE, p_n1, p_n2, p_h1);

    // 13) rest of MLP
    k_gemm_big<true, true, true><<<dim3(512 / GBN, BSZ * NV / GBM), 256>>>(
        p_h1, wc2, bc2, p_h2, BSZ * NV, 512, 512, 512);
    k_gemm<true, false><<<dim3(cdiv(30, BN), cdiv(BSZ * NV, BM)), 256>>>(
        p_h2, wc3, bc3, p_pred, BSZ * NV, 30, 512);

    // 14) split
    k_split<<<BSZ * NV, 32>>>(p_pred, out);
}